// round 1
// baseline (speedup 1.0000x reference)
#include <cuda_runtime.h>
#include <math.h>

#define B_  4
#define T_  1024
#define E_  1024
#define H_  16
#define HS_ 64
#define D_  1024
#define V_  32000
#define BT_ 4096

// ---------------- scratch (no allocations allowed) ----------------
__device__ float g_h[BT_ * E_];   // [B,T,E]
__device__ float g_q[BT_ * D_];   // [B,T,H,HS]
__device__ float g_k[BT_ * D_];
__device__ float g_v[BT_ * D_];
__device__ float g_o[BT_ * D_];   // [B,T,D] heads concatenated
__device__ float g_ff[BT_ * D_];
__device__ float g_loss[BT_];

// ---------------- embedding: h = tok_emb[x] + pos_emb[t] ----------------
__global__ __launch_bounds__(256) void embed_kernel(const int* __restrict__ x,
                                                    const float* __restrict__ tok,
                                                    const float* __restrict__ pos) {
    int idx = blockIdx.x * 256 + threadIdx.x;   // over BT_*E_/4 float4s
    int r = idx >> 8;                            // row (E_/4 = 256 float4 per row)
    int c = idx & 255;
    int token = x[r];
    int t = r & (T_ - 1);
    float4 a = ((const float4*)tok)[(size_t)token * 256 + c];
    float4 b = ((const float4*)pos)[(size_t)t * 256 + c];
    float4 o;
    o.x = a.x + b.x; o.y = a.y + b.y; o.z = a.z + b.z; o.w = a.w + b.w;
    ((float4*)g_h)[idx] = o;
}

// ---------------- generic fp32 GEMM: C[M,N] = A[M,K] @ B[K,N] (+bias)(+relu) ----
// HEADB: B is [H, K, 64] per-head layout (Wq/Wk/Wv), logical B[k][n] = W[n>>6][k][n&63]
template <int HEADB, int RELU, int HASBIAS>
__global__ __launch_bounds__(256) void gemm128_kernel(const float* __restrict__ A,
                                                      const float* __restrict__ Bm,
                                                      const float* __restrict__ bias,
                                                      float* __restrict__ C,
                                                      int M, int N, int K) {
    __shared__ float As[8][128];
    __shared__ float Bs[8][128];
    const int row0 = blockIdx.x * 128;
    const int col0 = blockIdx.y * 128;
    const int tid  = threadIdx.x;
    const int tx   = tid & 15;
    const int ty   = tid >> 4;

    float acc[8][8];
#pragma unroll
    for (int i = 0; i < 8; i++)
#pragma unroll
        for (int j = 0; j < 8; j++) acc[i][j] = 0.f;

    const int arow = tid >> 1;          // 0..127
    const int ak   = (tid & 1) * 4;     // 0 or 4
    const int brow = tid >> 5;          // 0..7
    const int bcol = (tid & 31) * 4;    // 0..124

    for (int k0 = 0; k0 < K; k0 += 8) {
        float4 av = *(const float4*)(A + (size_t)(row0 + arow) * K + k0 + ak);
        As[ak + 0][arow] = av.x;
        As[ak + 1][arow] = av.y;
        As[ak + 2][arow] = av.z;
        As[ak + 3][arow] = av.w;

        float4 bv;
        if (HEADB) {
            int n = col0 + bcol;
            bv = *(const float4*)(Bm + ((size_t)(n >> 6) * K + (k0 + brow)) * 64 + (n & 63));
        } else {
            bv = *(const float4*)(Bm + (size_t)(k0 + brow) * N + col0 + bcol);
        }
        *(float4*)&Bs[brow][bcol] = bv;

        __syncthreads();
#pragma unroll
        for (int kk = 0; kk < 8; kk++) {
            float a[8], b[8];
            *(float4*)&a[0] = *(const float4*)&As[kk][ty * 8];
            *(float4*)&a[4] = *(const float4*)&As[kk][ty * 8 + 4];
            *(float4*)&b[0] = *(const float4*)&Bs[kk][tx * 8];
            *(float4*)&b[4] = *(const float4*)&Bs[kk][tx * 8 + 4];
#pragma unroll
            for (int i = 0; i < 8; i++)
#pragma unroll
                for (int j = 0; j < 8; j++) acc[i][j] = fmaf(a[i], b[j], acc[i][j]);
        }
        __syncthreads();
    }

#pragma unroll
    for (int i = 0; i < 8; i++) {
        int r = row0 + ty * 8 + i;
#pragma unroll
        for (int j = 0; j < 8; j += 4) {
            int c = col0 + tx * 8 + j;
            float4 v;
            v.x = acc[i][j + 0]; v.y = acc[i][j + 1];
            v.z = acc[i][j + 2]; v.w = acc[i][j + 3];
            if (HASBIAS) {
                v.x += bias[c + 0]; v.y += bias[c + 1];
                v.z += bias[c + 2]; v.w += bias[c + 3];
            }
            if (RELU) {
                v.x = fmaxf(v.x, 0.f); v.y = fmaxf(v.y, 0.f);
                v.z = fmaxf(v.z, 0.f); v.w = fmaxf(v.w, 0.f);
            }
            *(float4*)(C + (size_t)r * N + c) = v;
        }
    }
}

// ---------------- causal attention with online softmax ----------------
// grid: (T_/128, B_*H_), 128 threads; thread = one query row.
// q/k/v layout: [B,T,H,HS]; output o: [B,T,D] (heads concatenated).
__global__ __launch_bounds__(128) void attn_kernel() {
    __shared__ float kv[64][64];     // K tile, then reused for V tile
    __shared__ float sc[64][128];    // scores [key][query-thread]
    const int z   = blockIdx.y;
    const int b   = z >> 4;
    const int hh  = z & 15;
    const int tid = threadIdx.x;
    const int t   = blockIdx.x * 128 + tid;

    const float* qp = g_q + ((size_t)(b * T_ + t) * H_ + hh) * HS_;
    float q[64];
#pragma unroll
    for (int d = 0; d < 64; d++) q[d] = qp[d] * 8.0f;   // scores * sqrt(HS)

    float acc[64];
#pragma unroll
    for (int d = 0; d < 64; d++) acc[d] = 0.f;
    float m = -INFINITY, l = 0.f;

    const int smax = blockIdx.x * 128 + 127;
    for (int s0 = 0; s0 <= smax; s0 += 64) {
        // load K tile (64 keys x 64 dims)
        const float* kbase = g_k + ((size_t)(b * T_ + s0) * H_ + hh) * HS_;
#pragma unroll
        for (int i = 0; i < 8; i++) {
            int lin = tid + 128 * i;
            int row = lin >> 4, c4 = lin & 15;
            *(float4*)&kv[row][c4 * 4] =
                *(const float4*)(kbase + (size_t)row * (H_ * HS_) + c4 * 4);
        }
        __syncthreads();

        int cnt = t - s0 + 1;
        cnt = cnt < 0 ? 0 : (cnt > 64 ? 64 : cnt);
        for (int j = 0; j < cnt; j++) {
            float s = 0.f;
#pragma unroll
            for (int d = 0; d < 64; d++) s = fmaf(q[d], kv[j][d], s);
            sc[j][tid] = s;
        }
        __syncthreads();

        // load V tile into the same buffer
        const float* vbase = g_v + ((size_t)(b * T_ + s0) * H_ + hh) * HS_;
#pragma unroll
        for (int i = 0; i < 8; i++) {
            int lin = tid + 128 * i;
            int row = lin >> 4, c4 = lin & 15;
            *(float4*)&kv[row][c4 * 4] =
                *(const float4*)(vbase + (size_t)row * (H_ * HS_) + c4 * 4);
        }
        __syncthreads();

        if (cnt > 0) {
            float tmax = -INFINITY;
            for (int j = 0; j < cnt; j++) tmax = fmaxf(tmax, sc[j][tid]);
            float mn = fmaxf(m, tmax);
            float scale = __expf(m - mn);   // 0 on first tile (m = -inf)
            l *= scale;
#pragma unroll
            for (int d = 0; d < 64; d++) acc[d] *= scale;
            for (int j = 0; j < cnt; j++) {
                float p = __expf(sc[j][tid] - mn);
                l += p;
#pragma unroll
                for (int d = 0; d < 64; d++) acc[d] = fmaf(p, kv[j][d], acc[d]);
            }
            m = mn;
        }
        __syncthreads();
    }

    float inv = 1.f / l;
    float* op = g_o + (size_t)(b * T_ + t) * D_ + hh * HS_;
#pragma unroll
    for (int d = 0; d < 64; d++) op[d] = acc[d] * inv;
}

// ---------------- loss: per-row log-softmax NLL, then mean ----------------
__global__ __launch_bounds__(256) void loss_row_kernel(const float* __restrict__ logits,
                                                       const int* __restrict__ y) {
    __shared__ float red[256];
    int row = blockIdx.x;
    int tid = threadIdx.x;
    const float* lr = logits + (size_t)row * V_;

    float mx = -INFINITY;
    for (int i = tid; i < V_; i += 256) mx = fmaxf(mx, lr[i]);
    red[tid] = mx;
    __syncthreads();
    for (int s = 128; s > 0; s >>= 1) {
        if (tid < s) red[tid] = fmaxf(red[tid], red[tid + s]);
        __syncthreads();
    }
    mx = red[0];
    __syncthreads();

    float sum = 0.f;
    for (int i = tid; i < V_; i += 256) sum += __expf(lr[i] - mx);
    red[tid] = sum;
    __syncthreads();
    for (int s = 128; s > 0; s >>= 1) {
        if (tid < s) red[tid] += red[tid + s];
        __syncthreads();
    }
    if (tid == 0) {
        float lse = mx + logf(red[0]);
        g_loss[row] = lse - lr[y[row]];
    }
}

__global__ __launch_bounds__(256) void loss_mean_kernel(float* out) {
    __shared__ float red[256];
    int tid = threadIdx.x;
    float s = 0.f;
    for (int i = tid; i < BT_; i += 256) s += g_loss[i];
    red[tid] = s;
    __syncthreads();
    for (int k = 128; k > 0; k >>= 1) {
        if (tid < k) red[tid] += red[tid + k];
        __syncthreads();
    }
    if (tid == 0) *out = red[0] / (float)BT_;
}

// ---------------- launch ----------------
extern "C" void kernel_launch(void* const* d_in, const int* in_sizes, int n_in,
                              void* d_out, int out_size) {
    const int*   x   = (const int*)d_in[0];
    const int*   y   = (const int*)d_in[1];
    const float* tok = (const float*)d_in[2];
    const float* pos = (const float*)d_in[3];
    const float* Wq  = (const float*)d_in[4];
    const float* Wk  = (const float*)d_in[5];
    const float* Wv  = (const float*)d_in[6];
    const float* ffw = (const float*)d_in[7];
    const float* ffb = (const float*)d_in[8];
    const float* fcw = (const float*)d_in[9];
    const float* fcb = (const float*)d_in[10];
    float* out = (float*)d_out;

    float *ph, *pq, *pk, *pv, *po, *pf;
    cudaGetSymbolAddress((void**)&ph, g_h);
    cudaGetSymbolAddress((void**)&pq, g_q);
    cudaGetSymbolAddress((void**)&pk, g_k);
    cudaGetSymbolAddress((void**)&pv, g_v);
    cudaGetSymbolAddress((void**)&po, g_o);
    cudaGetSymbolAddress((void**)&pf, g_ff);

    embed_kernel<<<(BT_ * E_ / 4) / 256, 256>>>(x, tok, pos);

    dim3 gqkv(BT_ / 128, D_ / 128);
    gemm128_kernel<1, 0, 0><<<gqkv, 256>>>(ph, Wq, nullptr, pq, BT_, D_, E_);
    gemm128_kernel<1, 0, 0><<<gqkv, 256>>>(ph, Wk, nullptr, pk, BT_, D_, E_);
    gemm128_kernel<1, 0, 0><<<gqkv, 256>>>(ph, Wv, nullptr, pv, BT_, D_, E_);

    dim3 gattn(T_ / 128, B_ * H_);
    attn_kernel<<<gattn, 128>>>();

    dim3 gff(BT_ / 128, D_ / 128);
    gemm128_kernel<0, 1, 1><<<gff, 256>>>(po, ffw, ffb, pf, BT_, D_, D_);

    dim3 glog(BT_ / 128, V_ / 128);
    gemm128_kernel<0, 0, 1><<<glog, 256>>>(pf, fcw, fcb, out, BT_, V_, D_);

    loss_row_kernel<<<BT_, 256>>>(out, y);

    long long logits_elems = (long long)BT_ * V_;
    if ((long long)out_size > logits_elems) {
        loss_mean_kernel<<<1, 256>>>(out + (size_t)logits_elems);
    }
}

// round 3
// speedup vs baseline: 2.2334x; 2.2334x over previous
#include <cuda_runtime.h>
#include <cuda_bf16.h>
#include <cstdint>
#include <math.h>

#define B_  4
#define T_  1024
#define E_  1024
#define H_  16
#define HS_ 64
#define D_  1024
#define V_  32000
#define BT_ 4096
#define QKV3 (3*D_)

// ---------------- scratch (device globals; no allocation allowed) ----------
__device__ __nv_bfloat16 g_hh[BT_*E_], g_hl[BT_*E_];        // embed split
__device__ float g_qkv[BT_*QKV3];                            // q|k|v fp32
__device__ __nv_bfloat16 g_oh[BT_*D_], g_ol[BT_*D_];        // attn out split
__device__ __nv_bfloat16 g_fh[BT_*D_], g_fl[BT_*D_];        // ff out split
__device__ __nv_bfloat16 g_wqkvh[QKV3*E_], g_wqkvl[QKV3*E_]; // [n][k]
__device__ __nv_bfloat16 g_wfh[D_*D_], g_wfl[D_*D_];
__device__ __nv_bfloat16 g_wch[V_*D_], g_wcl[V_*D_];
__device__ float g_loss[BT_];

// ---------------- embedding: h = tok_emb[x] + pos_emb[t], split to bf16 -----
__global__ __launch_bounds__(256) void embed_split(const int* __restrict__ x,
                                                   const float* __restrict__ tok,
                                                   const float* __restrict__ pos) {
    int idx = blockIdx.x * 256 + threadIdx.x;   // over BT_*E_/4 float4s
    int r = idx >> 8;
    int c = idx & 255;
    int token = x[r];
    int t = r & (T_ - 1);
    float4 a = ((const float4*)tok)[(size_t)token * 256 + c];
    float4 b = ((const float4*)pos)[(size_t)t * 256 + c];
    float v[4] = {a.x + b.x, a.y + b.y, a.z + b.z, a.w + b.w};
    __nv_bfloat16 h[4], l[4];
#pragma unroll
    for (int i = 0; i < 4; i++) {
        h[i] = __float2bfloat16(v[i]);
        l[i] = __float2bfloat16(v[i] - __bfloat162float(h[i]));
    }
    ((__nv_bfloat162*)g_hh)[idx * 2 + 0] = __halves2bfloat162(h[0], h[1]);
    ((__nv_bfloat162*)g_hh)[idx * 2 + 1] = __halves2bfloat162(h[2], h[3]);
    ((__nv_bfloat162*)g_hl)[idx * 2 + 0] = __halves2bfloat162(l[0], l[1]);
    ((__nv_bfloat162*)g_hl)[idx * 2 + 1] = __halves2bfloat162(l[2], l[3]);
}

// ---------------- weight transpose + split: W[K][N] -> hi/lo [N][K] --------
// HEADB: W is [H][K][64], logical W[k][n] = W[n>>6][k][n&63]
template <int HEADB>
__global__ __launch_bounds__(256) void wsplit(const float* __restrict__ W,
                                              __nv_bfloat16* __restrict__ hi,
                                              __nv_bfloat16* __restrict__ lo,
                                              int K, int N) {
    __shared__ float tile[32][33];
    int n0 = blockIdx.x * 32, k0 = blockIdx.y * 32;
    int tx = threadIdx.x & 31, ty = threadIdx.x >> 5;
#pragma unroll
    for (int j = 0; j < 4; j++) {
        int k = k0 + ty + j * 8, n = n0 + tx;
        float v = HEADB ? W[((size_t)(n >> 6) * K + k) * 64 + (n & 63)]
                        : W[(size_t)k * N + n];
        tile[ty + j * 8][tx] = v;
    }
    __syncthreads();
#pragma unroll
    for (int j = 0; j < 4; j++) {
        int n = n0 + ty + j * 8, k = k0 + tx;
        float v = tile[tx][ty + j * 8];
        __nv_bfloat16 h = __float2bfloat16(v);
        hi[(size_t)n * K + k] = h;
        lo[(size_t)n * K + k] = __float2bfloat16(v - __bfloat162float(h));
    }
}

// ---------------- split-bf16 tensor-core GEMM -------------------------------
// C[M,N] = (Ah+Al)[M,K] @ (Bh+Bl)^T[N,K]   (3 mma passes, fp32 accumulate)
#define SSTR 40                      // bf16 elems per smem row (32 + 8 pad)
#define ATILE (128*SSTR)             // elems per tile array
#define STAGE (4*ATILE)              // Ah,Al,Bh,Bl

__device__ __forceinline__ void cpa16(uint32_t dst, const void* src) {
    asm volatile("cp.async.cg.shared.global [%0], [%1], 16;\n" :: "r"(dst), "l"(src));
}
#define LDM4(R, ADDR) \
    asm volatile("ldmatrix.sync.aligned.m8n8.x4.shared.b16 {%0,%1,%2,%3}, [%4];" \
        : "=r"(R[0]), "=r"(R[1]), "=r"(R[2]), "=r"(R[3]) : "r"(ADDR))
#define MMA16816(Cc, Aa, B0, B1) \
    asm volatile("mma.sync.aligned.m16n8k16.row.col.f32.bf16.bf16.f32 " \
        "{%0,%1,%2,%3}, {%4,%5,%6,%7}, {%8,%9}, {%0,%1,%2,%3};" \
        : "+f"(Cc[0]), "+f"(Cc[1]), "+f"(Cc[2]), "+f"(Cc[3]) \
        : "r"(Aa[0]), "r"(Aa[1]), "r"(Aa[2]), "r"(Aa[3]), "r"(B0), "r"(B1))

template <int HASBIAS, int RELU, int SPLITOUT>
__global__ __launch_bounds__(256) void mma_gemm(
    const __nv_bfloat16* __restrict__ Ah, const __nv_bfloat16* __restrict__ Al,
    const __nv_bfloat16* __restrict__ Bh, const __nv_bfloat16* __restrict__ Bl,
    const float* __restrict__ bias, float* __restrict__ C,
    __nv_bfloat16* __restrict__ Ch, __nv_bfloat16* __restrict__ Cl,
    int M, int N, int K)
{
    extern __shared__ __nv_bfloat16 sm[];
    const int m0 = blockIdx.y * 128, n0 = blockIdx.x * 128;
    const int tid = threadIdx.x;
    const int lane = tid & 31, w = tid >> 5;
    const int wm = w >> 2, wn = w & 3;
    const uint32_t smb = (uint32_t)__cvta_generic_to_shared(sm);

    const int nk = K >> 5;

    auto load_stage = [&](int s, int k0) {
#pragma unroll
        for (int i = 0; i < 8; i++) {
            const int arr = i >> 1;               // 0:Ah 1:Al 2:Bh 3:Bl
            int rem = ((i & 1) << 8) + tid;       // 0..511
            int row = rem >> 2, seg = tid & 3;
            const __nv_bfloat16* gp = (arr == 0) ? Ah : (arr == 1) ? Al
                                     : (arr == 2) ? Bh : Bl;
            int grow = ((arr < 2) ? m0 : n0) + row;
            const __nv_bfloat16* src = gp + (size_t)grow * K + k0 + seg * 8;
            uint32_t dst = smb + (uint32_t)((s * STAGE + arr * ATILE + row * SSTR + seg * 8) << 1);
            cpa16(dst, src);
        }
        asm volatile("cp.async.commit_group;\n" ::: "memory");
    };

    load_stage(0, 0);
    load_stage(1, 32);

    float acc[4][4][4];
#pragma unroll
    for (int a = 0; a < 4; a++)
#pragma unroll
        for (int b = 0; b < 4; b++)
#pragma unroll
            for (int c = 0; c < 4; c++) acc[a][b][c] = 0.f;

    const int t8 = lane >> 3, r8 = lane & 7;

    for (int kt = 0; kt < nk; kt++) {
        asm volatile("cp.async.wait_group 1;\n" ::: "memory");
        __syncthreads();
        const uint32_t base = smb + (uint32_t)(((kt & 1) * STAGE) << 1);
#pragma unroll
        for (int kk = 0; kk < 2; kk++) {
            const int kof = kk << 4;
            uint32_t ah[4][4], al[4][4], bh[2][4], bl[2][4];
#pragma unroll
            for (int mt = 0; mt < 4; mt++) {
                int mrow = wm * 64 + mt * 16 + ((t8 & 1) << 3) + r8;
                int kcol = kof + ((t8 >> 1) << 3);
                uint32_t ad = base + (uint32_t)((mrow * SSTR + kcol) << 1);
                LDM4(ah[mt], ad);
                LDM4(al[mt], ad + (ATILE << 1));
            }
#pragma unroll
            for (int np = 0; np < 2; np++) {
                int nrow = wn * 32 + np * 16 + ((t8 >> 1) << 3) + r8;
                int kcol = kof + ((t8 & 1) << 3);
                uint32_t bd = base + (uint32_t)((2 * ATILE + nrow * SSTR + kcol) << 1);
                LDM4(bh[np], bd);
                LDM4(bl[np], bd + (ATILE << 1));
            }
#pragma unroll
            for (int mt = 0; mt < 4; mt++)
#pragma unroll
                for (int np = 0; np < 2; np++)
#pragma unroll
                    for (int hf = 0; hf < 2; hf++) {
                        float* cc = acc[mt][np * 2 + hf];
                        MMA16816(cc, ah[mt], bh[np][hf * 2], bh[np][hf * 2 + 1]);
                        MMA16816(cc, ah[mt], bl[np][hf * 2], bl[np][hf * 2 + 1]);
                        MMA16816(cc, al[mt], bh[np][hf * 2], bh[np][hf * 2 + 1]);
                    }
        }
        __syncthreads();
        if (kt + 2 < nk) load_stage(kt & 1, (kt + 2) << 5);
        else asm volatile("cp.async.commit_group;\n" ::: "memory");
    }

    // epilogue
#pragma unroll
    for (int mt = 0; mt < 4; mt++) {
#pragma unroll
        for (int nt = 0; nt < 4; nt++) {
            int col = n0 + wn * 32 + nt * 8 + ((lane & 3) << 1);
            float bv0 = 0.f, bv1 = 0.f;
            if (HASBIAS) { bv0 = bias[col]; bv1 = bias[col + 1]; }
#pragma unroll
            for (int hf = 0; hf < 2; hf++) {
                int row = m0 + wm * 64 + mt * 16 + (lane >> 2) + hf * 8;
                float v0 = acc[mt][nt][hf * 2 + 0] + bv0;
                float v1 = acc[mt][nt][hf * 2 + 1] + bv1;
                if (RELU) { v0 = fmaxf(v0, 0.f); v1 = fmaxf(v1, 0.f); }
                if (SPLITOUT) {
                    __nv_bfloat16 h0 = __float2bfloat16(v0);
                    __nv_bfloat16 h1 = __float2bfloat16(v1);
                    *(__nv_bfloat162*)(Ch + (size_t)row * N + col) = __halves2bfloat162(h0, h1);
                    *(__nv_bfloat162*)(Cl + (size_t)row * N + col) = __halves2bfloat162(
                        __float2bfloat16(v0 - __bfloat162float(h0)),
                        __float2bfloat16(v1 - __bfloat162float(h1)));
                } else {
                    float2 o; o.x = v0; o.y = v1;
                    *(float2*)(C + (size_t)row * N + col) = o;
                }
            }
        }
    }
}

// ---------------- causal attention (fp32, online softmax) -------------------
__global__ __launch_bounds__(128) void attn_kernel() {
    __shared__ float kv[64][64];
    __shared__ float sc[64][128];
    const int z   = blockIdx.y;
    const int b   = z >> 4;
    const int hh  = z & 15;
    const int tid = threadIdx.x;
    const int t   = blockIdx.x * 128 + tid;

    const float* qp = g_qkv + (size_t)(b * T_ + t) * QKV3 + hh * HS_;
    float q[64];
#pragma unroll
    for (int d = 0; d < 64; d++) q[d] = qp[d] * 8.0f;   // * sqrt(HS)

    float acc[64];
#pragma unroll
    for (int d = 0; d < 64; d++) acc[d] = 0.f;
    float m = -INFINITY, l = 0.f;

    const int smax = blockIdx.x * 128 + 127;
    for (int s0 = 0; s0 <= smax; s0 += 64) {
        const float* kbase = g_qkv + (size_t)(b * T_ + s0) * QKV3 + D_ + hh * HS_;
#pragma unroll
        for (int i = 0; i < 8; i++) {
            int lin = tid + 128 * i;
            int row = lin >> 4, c4 = lin & 15;
            *(float4*)&kv[row][c4 * 4] =
                *(const float4*)(kbase + (size_t)row * QKV3 + c4 * 4);
        }
        __syncthreads();

        int cnt = t - s0 + 1;
        cnt = cnt < 0 ? 0 : (cnt > 64 ? 64 : cnt);
        for (int j = 0; j < cnt; j++) {
            float s = 0.f;
#pragma unroll
            for (int d = 0; d < 64; d++) s = fmaf(q[d], kv[j][d], s);
            sc[j][tid] = s;
        }
        __syncthreads();

        const float* vbase = g_qkv + (size_t)(b * T_ + s0) * QKV3 + 2 * D_ + hh * HS_;
#pragma unroll
        for (int i = 0; i < 8; i++) {
            int lin = tid + 128 * i;
            int row = lin >> 4, c4 = lin & 15;
            *(float4*)&kv[row][c4 * 4] =
                *(const float4*)(vbase + (size_t)row * QKV3 + c4 * 4);
        }
        __syncthreads();

        if (cnt > 0) {
            float tmax = -INFINITY;
            for (int j = 0; j < cnt; j++) tmax = fmaxf(tmax, sc[j][tid]);
            float mn = fmaxf(m, tmax);
            float scale = __expf(m - mn);
            l *= scale;
#pragma unroll
            for (int d = 0; d < 64; d++) acc[d] *= scale;
            for (int j = 0; j < cnt; j++) {
                float p = __expf(sc[j][tid] - mn);
                l += p;
#pragma unroll
                for (int d = 0; d < 64; d++) acc[d] = fmaf(p, kv[j][d], acc[d]);
            }
            m = mn;
        }
        __syncthreads();
    }

    float inv = 1.f / l;
    size_t obase = (size_t)(b * T_ + t) * D_ + hh * HS_;
#pragma unroll
    for (int d = 0; d < 64; d++) {
        float v = acc[d] * inv;
        __nv_bfloat16 hv = __float2bfloat16(v);
        g_oh[obase + d] = hv;
        g_ol[obase + d] = __float2bfloat16(v - __bfloat162float(hv));
    }
}

// ---------------- loss ------------------------------------------------------
__global__ __launch_bounds__(256) void loss_row_kernel(const float* __restrict__ logits,
                                                       const int* __restrict__ y) {
    __shared__ float red[256];
    int row = blockIdx.x;
    int tid = threadIdx.x;
    const float* lr = logits + (size_t)row * V_;

    float mx = -INFINITY;
    for (int i = tid; i < V_; i += 256) mx = fmaxf(mx, lr[i]);
    red[tid] = mx;
    __syncthreads();
    for (int s = 128; s > 0; s >>= 1) {
        if (tid < s) red[tid] = fmaxf(red[tid], red[tid + s]);
        __syncthreads();
    }
    mx = red[0];
    __syncthreads();

    float sum = 0.f;
    for (int i = tid; i < V_; i += 256) sum += __expf(lr[i] - mx);
    red[tid] = sum;
    __syncthreads();
    for (int s = 128; s > 0; s >>= 1) {
        if (tid < s) red[tid] += red[tid + s];
        __syncthreads();
    }
    if (tid == 0) {
        float lse = mx + logf(red[0]);
        g_loss[row] = lse - lr[y[row]];
    }
}

__global__ __launch_bounds__(256) void loss_mean_kernel(float* out) {
    __shared__ float red[256];
    int tid = threadIdx.x;
    float s = 0.f;
    for (int i = tid; i < BT_; i += 256) s += g_loss[i];
    red[tid] = s;
    __syncthreads();
    for (int k = 128; k > 0; k >>= 1) {
        if (tid < k) red[tid] += red[tid + k];
        __syncthreads();
    }
    if (tid == 0) *out = red[0] / (float)BT_;
}

// ---------------- launch ----------------------------------------------------
extern "C" void kernel_launch(void* const* d_in, const int* in_sizes, int n_in,
                              void* d_out, int out_size) {
    const int*   x   = (const int*)d_in[0];
    const int*   y   = (const int*)d_in[1];
    const float* tok = (const float*)d_in[2];
    const float* pos = (const float*)d_in[3];
    const float* Wq  = (const float*)d_in[4];
    const float* Wk  = (const float*)d_in[5];
    const float* Wv  = (const float*)d_in[6];
    const float* ffw = (const float*)d_in[7];
    const float* ffb = (const float*)d_in[8];
    const float* fcw = (const float*)d_in[9];
    const float* fcb = (const float*)d_in[10];
    float* out = (float*)d_out;

    __nv_bfloat16 *phh, *phl, *poh, *pol, *pfh, *pfl;
    __nv_bfloat16 *pwqh, *pwql, *pwfh, *pwfl, *pwch, *pwcl;
    float *pqkv;
    cudaGetSymbolAddress((void**)&phh, g_hh);
    cudaGetSymbolAddress((void**)&phl, g_hl);
    cudaGetSymbolAddress((void**)&poh, g_oh);
    cudaGetSymbolAddress((void**)&pol, g_ol);
    cudaGetSymbolAddress((void**)&pfh, g_fh);
    cudaGetSymbolAddress((void**)&pfl, g_fl);
    cudaGetSymbolAddress((void**)&pwqh, g_wqkvh);
    cudaGetSymbolAddress((void**)&pwql, g_wqkvl);
    cudaGetSymbolAddress((void**)&pwfh, g_wfh);
    cudaGetSymbolAddress((void**)&pwfl, g_wfl);
    cudaGetSymbolAddress((void**)&pwch, g_wch);
    cudaGetSymbolAddress((void**)&pwcl, g_wcl);
    cudaGetSymbolAddress((void**)&pqkv, g_qkv);

    const int smem = 2 * STAGE * 2;  // bytes (two stages of bf16)
    cudaFuncSetAttribute(mma_gemm<0,0,0>, cudaFuncAttributeMaxDynamicSharedMemorySize, smem);
    cudaFuncSetAttribute(mma_gemm<1,1,1>, cudaFuncAttributeMaxDynamicSharedMemorySize, smem);
    cudaFuncSetAttribute(mma_gemm<1,0,0>, cudaFuncAttributeMaxDynamicSharedMemorySize, smem);

    // embedding (writes split h)
    embed_split<<<(BT_ * E_ / 4) / 256, 256>>>(x, tok, pos);

    // weight conversions (transpose + split)
    wsplit<1><<<dim3(D_/32, E_/32), 256>>>(Wq, pwqh,            pwql,            E_, D_);
    wsplit<1><<<dim3(D_/32, E_/32), 256>>>(Wk, pwqh + D_*E_,    pwql + D_*E_,    E_, D_);
    wsplit<1><<<dim3(D_/32, E_/32), 256>>>(Wv, pwqh + 2*D_*E_,  pwql + 2*D_*E_,  E_, D_);
    wsplit<0><<<dim3(D_/32, D_/32), 256>>>(ffw, pwfh, pwfl, D_, D_);
    wsplit<0><<<dim3(V_/32, D_/32), 256>>>(fcw, pwch, pwcl, D_, V_);

    // fused QKV GEMM: [4096,3072] = h @ [Wq|Wk|Wv]
    mma_gemm<0,0,0><<<dim3(QKV3/128, BT_/128), 256, smem>>>(
        phh, phl, pwqh, pwql, nullptr, pqkv, nullptr, nullptr, BT_, QKV3, E_);

    // attention
    attn_kernel<<<dim3(T_/128, B_*H_), 128>>>();

    // FF: relu(o @ ff_w + ff_b), split output
    mma_gemm<1,1,1><<<dim3(D_/128, BT_/128), 256, smem>>>(
        poh, pol, pwfh, pwfl, ffb, nullptr, pfh, pfl, BT_, D_, D_);

    // logits: ff @ fc_w + fc_b -> d_out fp32
    mma_gemm<1,0,0><<<dim3(V_/128, BT_/128), 256, smem>>>(
        pfh, pfl, pwch, pwcl, fcb, out, nullptr, nullptr, BT_, V_, D_);

    // loss
    loss_row_kernel<<<BT_, 256>>>(out, y);
    long long logits_elems = (long long)BT_ * V_;
    if ((long long)out_size > logits_elems) {
        loss_mean_kernel<<<1, 256>>>(out + (size_t)logits_elems);
    }
}

// round 5
// speedup vs baseline: 2.9223x; 1.3084x over previous
#include <cuda_runtime.h>
#include <cuda_fp16.h>
#include <cstdint>
#include <math.h>

#define B_  4
#define T_  1024
#define E_  1024
#define H_  16
#define HS_ 64
#define D_  1024
#define V_  32000
#define BT_ 4096
#define QKV3 (3*D_)
#define PN_  (V_/32)        // LSE partials per row: (V/128 col blocks) * 4 warps

// ---------------- scratch (device globals; no allocation allowed) ----------
__device__ __half g_hh[BT_*E_], g_hl[BT_*E_];          // embed split
__device__ float  g_qkv[BT_*QKV3];                      // q|k|v fp32
__device__ __half g_oh[BT_*D_], g_ol[BT_*D_];          // attn out split
__device__ __half g_fh[BT_*D_], g_fl[BT_*D_];          // ff out split
__device__ __half g_wqkvh[QKV3*E_], g_wqkvl[QKV3*E_];  // [n][k]
__device__ __half g_wfh[D_*D_], g_wfl[D_*D_];
__device__ __half g_wch[V_*D_];                         // fc weights hi only (2-pass)
__device__ float  g_pm[(size_t)BT_*PN_], g_ps[(size_t)BT_*PN_];
__device__ float  g_loss[BT_];

// ---------------- embedding: h = tok_emb[x] + pos_emb[t], split to fp16 -----
__global__ __launch_bounds__(256) void embed_split(const int* __restrict__ x,
                                                   const float* __restrict__ tok,
                                                   const float* __restrict__ pos) {
    int idx = blockIdx.x * 256 + threadIdx.x;   // over BT_*E_/4 float4s
    int r = idx >> 8;
    int c = idx & 255;
    int token = x[r];
    int t = r & (T_ - 1);
    float4 a = ((const float4*)tok)[(size_t)token * 256 + c];
    float4 b = ((const float4*)pos)[(size_t)t * 256 + c];
    float v[4] = {a.x + b.x, a.y + b.y, a.z + b.z, a.w + b.w};
    __half h[4], l[4];
#pragma unroll
    for (int i = 0; i < 4; i++) {
        h[i] = __float2half(v[i]);
        l[i] = __float2half(v[i] - __half2float(h[i]));
    }
    ((__half2*)g_hh)[idx * 2 + 0] = __halves2half2(h[0], h[1]);
    ((__half2*)g_hh)[idx * 2 + 1] = __halves2half2(h[2], h[3]);
    ((__half2*)g_hl)[idx * 2 + 0] = __halves2half2(l[0], l[1]);
    ((__half2*)g_hl)[idx * 2 + 1] = __halves2half2(l[2], l[3]);
}

// ---------------- weight transpose + split: W[K][N] -> hi(/lo) [N][K] ------
// HEADB: W is [H][K][64], logical W[k][n] = W[n>>6][k][n&63]
template <int HEADB, int WLO>
__global__ __launch_bounds__(256) void wsplit(const float* __restrict__ W,
                                              __half* __restrict__ hi,
                                              __half* __restrict__ lo,
                                              int K, int N) {
    __shared__ float tile[32][33];
    int n0 = blockIdx.x * 32, k0 = blockIdx.y * 32;
    int tx = threadIdx.x & 31, ty = threadIdx.x >> 5;
#pragma unroll
    for (int j = 0; j < 4; j++) {
        int k = k0 + ty + j * 8, n = n0 + tx;
        float v = HEADB ? W[((size_t)(n >> 6) * K + k) * 64 + (n & 63)]
                        : W[(size_t)k * N + n];
        tile[ty + j * 8][tx] = v;
    }
    __syncthreads();
#pragma unroll
    for (int j = 0; j < 4; j++) {
        int n = n0 + ty + j * 8, k = k0 + tx;
        float v = tile[tx][ty + j * 8];
        __half h = __float2half(v);
        hi[(size_t)n * K + k] = h;
        if (WLO) lo[(size_t)n * K + k] = __float2half(v - __half2float(h));
    }
}

// ---------------- split-fp16 tensor-core GEMM -------------------------------
// NP=3: C = ah*bh + ah*bl + al*bh (err ~2^-22)
// NP=2: C = ah*bh + al*bh = a*bh  (err ~2^-12 stochastic; logits only)
#define SSTR 40                      // fp16 elems per smem row (32 + 8 pad)
#define ATILE (128*SSTR)             // elems per tile array

__device__ __forceinline__ void cpa16(uint32_t dst, const void* src) {
    asm volatile("cp.async.cg.shared.global [%0], [%1], 16;\n" :: "r"(dst), "l"(src));
}
#define LDM4(R, ADDR) \
    asm volatile("ldmatrix.sync.aligned.m8n8.x4.shared.b16 {%0,%1,%2,%3}, [%4];" \
        : "=r"(R[0]), "=r"(R[1]), "=r"(R[2]), "=r"(R[3]) : "r"(ADDR))
#define MMAF16(Cc, Aa, B0, B1) \
    asm volatile("mma.sync.aligned.m16n8k16.row.col.f32.f16.f16.f32 " \
        "{%0,%1,%2,%3}, {%4,%5,%6,%7}, {%8,%9}, {%0,%1,%2,%3};" \
        : "+f"(Cc[0]), "+f"(Cc[1]), "+f"(Cc[2]), "+f"(Cc[3]) \
        : "r"(Aa[0]), "r"(Aa[1]), "r"(Aa[2]), "r"(Aa[3]), "r"(B0), "r"(B1))

template <int NP, int HASBIAS, int RELU, int SPLITOUT, int LSE>
__global__ __launch_bounds__(256) void mma_gemm(
    const __half* __restrict__ Ah, const __half* __restrict__ Al,
    const __half* __restrict__ Bh, const __half* __restrict__ Bl,
    const float* __restrict__ bias, float* __restrict__ C,
    __half* __restrict__ Ch, __half* __restrict__ Cl,
    int M, int N, int K)
{
    extern __shared__ __half sm[];
    constexpr int NARR = (NP == 3) ? 4 : 3;
    constexpr int STG  = NARR * ATILE;
    const int m0 = blockIdx.x * 128, n0 = blockIdx.y * 128;   // rows fastest
    const int tid = threadIdx.x;
    const int lane = tid & 31, w = tid >> 5;
    const int wm = w >> 2, wn = w & 3;
    const uint32_t smb = (uint32_t)__cvta_generic_to_shared(sm);

    const int nk = K >> 5;

    auto load_stage = [&](int s, int k0) {
#pragma unroll
        for (int i = 0; i < 2 * NARR; i++) {
            const int arr = i >> 1;               // 0:Ah 1:Al 2:Bh 3:Bl
            int rem = ((i & 1) << 8) + tid;       // 0..511
            int row = rem >> 2, seg = tid & 3;
            const __half* gp = (arr == 0) ? Ah : (arr == 1) ? Al
                             : (arr == 2) ? Bh : Bl;
            int grow = ((arr < 2) ? m0 : n0) + row;
            const __half* src = gp + (size_t)grow * K + k0 + seg * 8;
            uint32_t dst = smb + (uint32_t)((s * STG + arr * ATILE + row * SSTR + seg * 8) << 1);
            cpa16(dst, src);
        }
        asm volatile("cp.async.commit_group;\n" ::: "memory");
    };

    load_stage(0, 0);
    load_stage(1, 32);

    float acc[4][4][4];
#pragma unroll
    for (int a = 0; a < 4; a++)
#pragma unroll
        for (int b = 0; b < 4; b++)
#pragma unroll
            for (int c = 0; c < 4; c++) acc[a][b][c] = 0.f;

    const int t8 = lane >> 3, r8 = lane & 7;

    for (int kt = 0; kt < nk; kt++) {
        asm volatile("cp.async.wait_group 1;\n" ::: "memory");
        __syncthreads();
        const uint32_t base = smb + (uint32_t)(((kt & 1) * STG) << 1);
#pragma unroll
        for (int kk = 0; kk < 2; kk++) {
            const int kof = kk << 4;
            uint32_t ah[4][4], al[4][4], bh[2][4], bl[2][4];
#pragma unroll
            for (int mt = 0; mt < 4; mt++) {
                int mrow = wm * 64 + mt * 16 + ((t8 & 1) << 3) + r8;
                int kcol = kof + ((t8 >> 1) << 3);
                uint32_t ad = base + (uint32_t)((mrow * SSTR + kcol) << 1);
                LDM4(ah[mt], ad);
                LDM4(al[mt], ad + (ATILE << 1));
            }
#pragma unroll
            for (int np = 0; np < 2; np++) {
                int nrow = wn * 32 + np * 16 + ((t8 >> 1) << 3) + r8;
                int kcol = kof + ((t8 & 1) << 3);
                uint32_t bd = base + (uint32_t)((2 * ATILE + nrow * SSTR + kcol) << 1);
                LDM4(bh[np], bd);
                if (NP == 3) LDM4(bl[np], bd + (ATILE << 1));
            }
#pragma unroll
            for (int mt = 0; mt < 4; mt++)
#pragma unroll
                for (int np = 0; np < 2; np++)
#pragma unroll
                    for (int hf = 0; hf < 2; hf++) {
                        float* cc = acc[mt][np * 2 + hf];
                        MMAF16(cc, ah[mt], bh[np][hf * 2], bh[np][hf * 2 + 1]);
                        MMAF16(cc, al[mt], bh[np][hf * 2], bh[np][hf * 2 + 1]);
                        if (NP == 3)
                            MMAF16(cc, ah[mt], bl[np][hf * 2], bl[np][hf * 2 + 1]);
                    }
        }
        __syncthreads();
        if (kt + 2 < nk) load_stage(kt & 1, (kt + 2) << 5);
        else asm volatile("cp.async.commit_group;\n" ::: "memory");
    }

    // ---------------- epilogue ----------------
    float bj[8];
#pragma unroll
    for (int nt = 0; nt < 4; nt++) {
        int col = n0 + wn * 32 + nt * 8 + ((lane & 3) << 1);
        bj[nt * 2 + 0] = HASBIAS ? bias[col] : 0.f;
        bj[nt * 2 + 1] = HASBIAS ? bias[col + 1] : 0.f;
    }
#pragma unroll
    for (int mt = 0; mt < 4; mt++) {
#pragma unroll
        for (int hf = 0; hf < 2; hf++) {
            int row = m0 + wm * 64 + mt * 16 + (lane >> 2) + hf * 8;
            float vv[8];
            float vmax = -INFINITY;
#pragma unroll
            for (int nt = 0; nt < 4; nt++) {
#pragma unroll
                for (int j = 0; j < 2; j++) {
                    float v = acc[mt][nt][hf * 2 + j] + bj[nt * 2 + j];
                    if (RELU) v = fmaxf(v, 0.f);
                    vv[nt * 2 + j] = v;
                    vmax = fmaxf(vmax, v);
                }
            }
#pragma unroll
            for (int nt = 0; nt < 4; nt++) {
                int col = n0 + wn * 32 + nt * 8 + ((lane & 3) << 1);
                if (SPLITOUT) {
                    __half h0 = __float2half(vv[nt * 2]);
                    __half h1 = __float2half(vv[nt * 2 + 1]);
                    *(__half2*)(Ch + (size_t)row * N + col) = __halves2half2(h0, h1);
                    *(__half2*)(Cl + (size_t)row * N + col) = __halves2half2(
                        __float2half(vv[nt * 2] - __half2float(h0)),
                        __float2half(vv[nt * 2 + 1] - __half2float(h1)));
                } else {
                    float2 o; o.x = vv[nt * 2]; o.y = vv[nt * 2 + 1];
                    *(float2*)(C + (size_t)row * N + col) = o;
                }
            }
            if (LSE) {
                float rs = 0.f;
#pragma unroll
                for (int k = 0; k < 8; k++) rs += __expf(vv[k] - vmax);
                float rm = vmax;
#pragma unroll
                for (int off = 1; off <= 2; off <<= 1) {
                    float m2 = __shfl_xor_sync(0xFFFFFFFFu, rm, off);
                    float s2 = __shfl_xor_sync(0xFFFFFFFFu, rs, off);
                    float mn = fmaxf(rm, m2);
                    rs = rs * __expf(rm - mn) + s2 * __expf(m2 - mn);
                    rm = mn;
                }
                if ((lane & 3) == 0) {
                    int pcol = blockIdx.y * 4 + wn;
                    g_pm[(size_t)row * PN_ + pcol] = rm;
                    g_ps[(size_t)row * PN_ + pcol] = rs;
                }
            }
        }
    }
}

// ---------------- causal attention (fp32, online softmax) -------------------
__global__ __launch_bounds__(128) void attn_kernel() {
    __shared__ float kv[64][64];
    __shared__ float sc[64][128];
    const int z   = blockIdx.y;
    const int b   = z >> 4;
    const int hh  = z & 15;
    const int tid = threadIdx.x;
    const int t   = blockIdx.x * 128 + tid;

    const float* qp = g_qkv + (size_t)(b * T_ + t) * QKV3 + hh * HS_;
    float q[64];
#pragma unroll
    for (int d = 0; d < 64; d++) q[d] = qp[d] * 8.0f;   // * sqrt(HS)

    float acc[64];
#pragma unroll
    for (int d = 0; d < 64; d++) acc[d] = 0.f;
    float m = -INFINITY, l = 0.f;

    const int smax = blockIdx.x * 128 + 127;
    for (int s0 = 0; s0 <= smax; s0 += 64) {
        const float* kbase = g_qkv + (size_t)(b * T_ + s0) * QKV3 + D_ + hh * HS_;
#pragma unroll
        for (int i = 0; i < 8; i++) {
            int lin = tid + 128 * i;
            int row = lin >> 4, c4 = lin & 15;
            *(float4*)&kv[row][c4 * 4] =
                *(const float4*)(kbase + (size_t)row * QKV3 + c4 * 4);
        }
        __syncthreads();

        int cnt = t - s0 + 1;
        cnt = cnt < 0 ? 0 : (cnt > 64 ? 64 : cnt);
        for (int j = 0; j < cnt; j++) {
            float s = 0.f;
#pragma unroll
            for (int d = 0; d < 64; d++) s = fmaf(q[d], kv[j][d], s);
            sc[j][tid] = s;
        }
        __syncthreads();

        const float* vbase = g_qkv + (size_t)(b * T_ + s0) * QKV3 + 2 * D_ + hh * HS_;
#pragma unroll
        for (int i = 0; i < 8; i++) {
            int lin = tid + 128 * i;
            int row = lin >> 4, c4 = lin & 15;
            *(float4*)&kv[row][c4 * 4] =
                *(const float4*)(vbase + (size_t)row * QKV3 + c4 * 4);
        }
        __syncthreads();

        if (cnt > 0) {
            float tmax = -INFINITY;
            for (int j = 0; j < cnt; j++) tmax = fmaxf(tmax, sc[j][tid]);
            float mn = fmaxf(m, tmax);
            float scale = __expf(m - mn);
            l *= scale;
#pragma unroll
            for (int d = 0; d < 64; d++) acc[d] *= scale;
            for (int j = 0; j < cnt; j++) {
                float p = __expf(sc[j][tid] - mn);
                l += p;
#pragma unroll
                for (int d = 0; d < 64; d++) acc[d] = fmaf(p, kv[j][d], acc[d]);
            }
            m = mn;
        }
        __syncthreads();
    }

    float inv = 1.f / l;
    size_t obase = (size_t)(b * T_ + t) * D_ + hh * HS_;
#pragma unroll
    for (int d = 0; d < 64; d++) {
        float v = acc[d] * inv;
        __half hv = __float2half(v);
        g_oh[obase + d] = hv;
        g_ol[obase + d] = __float2half(v - __half2float(hv));
    }
}

// ---------------- loss from LSE partials -------------------------------------
__global__ __launch_bounds__(256) void loss_partial_kernel(const float* __restrict__ logits,
                                                           const int* __restrict__ y) {
    __shared__ float sm_m[256], sm_s[256];
    int row = blockIdx.x;
    int tid = threadIdx.x;
    float m = -INFINITY, s = 0.f;
    for (int i = tid; i < PN_; i += 256) {
        float m2 = g_pm[(size_t)row * PN_ + i];
        float s2 = g_ps[(size_t)row * PN_ + i];
        float mn = fmaxf(m, m2);
        s = s * __expf(m - mn) + s2 * __expf(m2 - mn);
        m = mn;
    }
    sm_m[tid] = m; sm_s[tid] = s;
    __syncthreads();
    for (int k = 128; k > 0; k >>= 1) {
        if (tid < k) {
            float m2 = sm_m[tid + k], s2 = sm_s[tid + k];
            float mn = fmaxf(sm_m[tid], m2);
            sm_s[tid] = sm_s[tid] * __expf(sm_m[tid] - mn) + s2 * __expf(m2 - mn);
            sm_m[tid] = mn;
        }
        __syncthreads();
    }
    if (tid == 0) {
        g_loss[row] = sm_m[0] + logf(sm_s[0]) - logits[(size_t)row * V_ + y[row]];
    }
}

__global__ __launch_bounds__(256) void loss_mean_kernel(float* out) {
    __shared__ float red[256];
    int tid = threadIdx.x;
    float s = 0.f;
    for (int i = tid; i < BT_; i += 256) s += g_loss[i];
    red[tid] = s;
    __syncthreads();
    for (int k = 128; k > 0; k >>= 1) {
        if (tid < k) red[tid] += red[tid + k];
        __syncthreads();
    }
    if (tid == 0) *out = red[0] / (float)BT_;
}

// ---------------- launch ----------------------------------------------------
extern "C" void kernel_launch(void* const* d_in, const int* in_sizes, int n_in,
                              void* d_out, int out_size) {
    const int*   x   = (const int*)d_in[0];
    const int*   y   = (const int*)d_in[1];
    const float* tok = (const float*)d_in[2];
    const float* pos = (const float*)d_in[3];
    const float* Wq  = (const float*)d_in[4];
    const float* Wk  = (const float*)d_in[5];
    const float* Wv  = (const float*)d_in[6];
    const float* ffw = (const float*)d_in[7];
    const float* ffb = (const float*)d_in[8];
    const float* fcw = (const float*)d_in[9];
    const float* fcb = (const float*)d_in[10];
    float* out = (float*)d_out;

    __half *phh, *phl, *poh, *pol, *pfh, *pfl;
    __half *pwqh, *pwql, *pwfh, *pwfl, *pwch;
    float *pqkv;
    cudaGetSymbolAddress((void**)&phh, g_hh);
    cudaGetSymbolAddress((void**)&phl, g_hl);
    cudaGetSymbolAddress((void**)&poh, g_oh);
    cudaGetSymbolAddress((void**)&pol, g_ol);
    cudaGetSymbolAddress((void**)&pfh, g_fh);
    cudaGetSymbolAddress((void**)&pfl, g_fl);
    cudaGetSymbolAddress((void**)&pwqh, g_wqkvh);
    cudaGetSymbolAddress((void**)&pwql, g_wqkvl);
    cudaGetSymbolAddress((void**)&pwfh, g_wfh);
    cudaGetSymbolAddress((void**)&pwfl, g_wfl);
    cudaGetSymbolAddress((void**)&pwch, g_wch);
    cudaGetSymbolAddress((void**)&pqkv, g_qkv);

    const int smem3 = 2 * 4 * ATILE * 2;   // 81920 B (3-pass: Ah,Al,Bh,Bl x2 stages)
    const int smem2 = 2 * 3 * ATILE * 2;   // 61440 B (2-pass: Ah,Al,Bh x2 stages)
    cudaFuncSetAttribute(mma_gemm<3,0,0,0,0>, cudaFuncAttributeMaxDynamicSharedMemorySize, smem3);
    cudaFuncSetAttribute(mma_gemm<3,1,1,1,0>, cudaFuncAttributeMaxDynamicSharedMemorySize, smem3);
    cudaFuncSetAttribute(mma_gemm<2,1,0,0,1>, cudaFuncAttributeMaxDynamicSharedMemorySize, smem2);

    // embedding (writes split h)
    embed_split<<<(BT_ * E_ / 4) / 256, 256>>>(x, tok, pos);

    // weight conversions (transpose + split)
    wsplit<1,1><<<dim3(D_/32, E_/32), 256>>>(Wq, pwqh,           pwql,           E_, D_);
    wsplit<1,1><<<dim3(D_/32, E_/32), 256>>>(Wk, pwqh + D_*E_,   pwql + D_*E_,   E_, D_);
    wsplit<1,1><<<dim3(D_/32, E_/32), 256>>>(Wv, pwqh + 2*D_*E_, pwql + 2*D_*E_, E_, D_);
    wsplit<0,1><<<dim3(D_/32, D_/32), 256>>>(ffw, pwfh, pwfl, D_, D_);
    wsplit<0,0><<<dim3(V_/32, D_/32), 256>>>(fcw, pwch, nullptr, D_, V_);

    // fused QKV GEMM: [4096,3072] = h @ [Wq|Wk|Wv]^T  (3-pass)
    mma_gemm<3,0,0,0,0><<<dim3(BT_/128, QKV3/128), 256, smem3>>>(
        phh, phl, pwqh, pwql, nullptr, pqkv, nullptr, nullptr, BT_, QKV3, E_);

    // attention
    attn_kernel<<<dim3(T_/128, B_*H_), 128>>>();

    // FF: relu(o @ ff_w + ff_b), split output (3-pass)
    mma_gemm<3,1,1,1,0><<<dim3(BT_/128, D_/128), 256, smem3>>>(
        poh, pol, pwfh, pwfl, ffb, nullptr, pfh, pfl, BT_, D_, D_);

    // logits: ff @ fc_w + fc_b -> d_out fp32 (2-pass, fused LSE partials)
    mma_gemm<2,1,0,0,1><<<dim3(BT_/128, V_/128), 256, smem2>>>(
        pfh, pfl, pwch, nullptr, fcb, out, nullptr, nullptr, BT_, V_, D_);

    // loss
    loss_partial_kernel<<<BT_, 256>>>(out, y);
    long long logits_elems = (long long)BT_ * V_;
    if ((long long)out_size > logits_elems) {
        loss_mean_kernel<<<1, 256>>>(out + (size_t)logits_elems);
    }
}